// round 5
// baseline (speedup 1.0000x reference)
#include <cuda_runtime.h>
#include <cstdint>

// IOVPreTrainedEmbeddings: out[b,s,:] = (oov_map[x[b,s]] >= 0)
//                                         ? oov_embed[oov_map[x[b,s]], :]
//                                         : w2v[x[b,s], :]
//
// x [128,1024] i32, w2v [100000,300] f32, oov_embed [5000,300] f32,
// oov_map [100000] i32, out [128,1024,300] f32.
//
// R4: ILP=8. R3 (ILP=4) landed DRAM=69.3%, issue=14.5%, occ=81.5% —
// still latency-bound on the id->map->payload chain, not issue/occupancy
// bound. Double the in-flight payload per warp. True floor ~30us
// (157MB writes must hit DRAM; reads are ~2/3 L2-served since the 120MB
// w2v table nearly fits in the 126MB L2).

static constexpr int TOKENS = 128 * 1024;     // B*S
static constexpr int DIM    = 300;
static constexpr int VEC    = DIM / 4;        // 75 float4 per row (1200B stride)
static constexpr long long TOTAL4 = (long long)TOKENS * VEC;  // 9,830,400

static constexpr int THREADS = 256;
static constexpr int UNROLL  = 8;
static constexpr int BLOCKS  = (int)(TOTAL4 / ((long long)THREADS * UNROLL)); // 4800, exact
static constexpr int STRIDE  = THREADS * BLOCKS;  // 1,228,800

__global__ __launch_bounds__(THREADS)
void iov_gather_ilp8_kernel(const int*    __restrict__ x,
                            const float4* __restrict__ w2v,       // row stride VEC
                            const float4* __restrict__ oov_embed, // row stride VEC
                            const int*    __restrict__ oov_map,
                            float4*       __restrict__ out)
{
    const int base = blockIdx.x * THREADS + threadIdx.x;

    int id[UNROLL];
    int row[UNROLL];
    float4 val[UNROLL];

    // Phase 1: token ids — 8 independent L1/L2-resident loads in flight.
    #pragma unroll
    for (int k = 0; k < UNROLL; k++) {
        int token = (base + k * STRIDE) / VEC;   // mul-shift div by 75
        id[k] = __ldg(&x[token]);
    }

    // Phase 2: oov_map gathers — 8 in flight.
    #pragma unroll
    for (int k = 0; k < UNROLL; k++)
        row[k] = __ldg(&oov_map[id[k]]);

    // Phase 3: payload gathers (DRAM/L2-bound) — 8 in flight.
    #pragma unroll
    for (int k = 0; k < UNROLL; k++) {
        int i     = base + k * STRIDE;
        int token = i / VEC;
        int chunk = i - token * VEC;
        const float4* src = (row[k] >= 0)
            ? (oov_embed + (long long)row[k] * VEC + chunk)
            : (w2v       + (long long)id[k]  * VEC + chunk);
        val[k] = __ldg(src);
    }

    // Phase 4: coalesced stores.
    #pragma unroll
    for (int k = 0; k < UNROLL; k++)
        out[base + k * STRIDE] = val[k];
}

extern "C" void kernel_launch(void* const* d_in, const int* in_sizes, int n_in,
                              void* d_out, int out_size)
{
    const int*    x         = (const int*)   d_in[0];
    const float4* w2v       = (const float4*)d_in[1];
    const float4* oov_embed = (const float4*)d_in[2];
    const int*    oov_map   = (const int*)   d_in[3];
    float4*       out       = (float4*)d_out;

    iov_gather_ilp8_kernel<<<BLOCKS, THREADS>>>(x, w2v, oov_embed, oov_map, out);
}

// round 6
// speedup vs baseline: 1.0129x; 1.0129x over previous
#include <cuda_runtime.h>
#include <cstdint>

// IOVPreTrainedEmbeddings: out[b,s,:] = (oov_map[x[b,s]] >= 0)
//                                         ? oov_embed[oov_map[x[b,s]], :]
//                                         : w2v[x[b,s], :]
//
// x [128,1024] i32, w2v [100000,300] f32, oov_embed [5000,300] f32,
// oov_map [100000] i32, out [128,1024,300] f32.
//
// R5: streaming stores. R4 showed ILP 4->8 changed nothing (regs pinned at
// 32; ptxas re-interleaves, MLP_eff ~4). New model: the 157MB output write
// stream allocates in L2 and evicts the 120MB w2v table (L2 = 126MB), so
// reads that could be L2 hits (graph replays keep the table warm) go to
// DRAM. __stcs (evict-first) keeps w2v resident; kernel becomes write-bound.

static constexpr int TOKENS = 128 * 1024;     // B*S
static constexpr int DIM    = 300;
static constexpr int VEC    = DIM / 4;        // 75 float4 per row (1200B stride)
static constexpr long long TOTAL4 = (long long)TOKENS * VEC;  // 9,830,400

static constexpr int THREADS = 256;
static constexpr int UNROLL  = 8;
static constexpr int BLOCKS  = (int)(TOTAL4 / ((long long)THREADS * UNROLL)); // 4800, exact
static constexpr int STRIDE  = THREADS * BLOCKS;  // 1,228,800

__global__ __launch_bounds__(THREADS)
void iov_gather_cs_kernel(const int*    __restrict__ x,
                          const float4* __restrict__ w2v,       // row stride VEC
                          const float4* __restrict__ oov_embed, // row stride VEC
                          const int*    __restrict__ oov_map,
                          float4*       __restrict__ out)
{
    const int base = blockIdx.x * THREADS + threadIdx.x;

    int id[UNROLL];
    int row[UNROLL];

    // Phase 1: token ids — L1/L2-resident, broadcast across the 75 threads
    // of each token.
    #pragma unroll
    for (int k = 0; k < UNROLL; k++) {
        int token = (base + k * STRIDE) / VEC;   // mul-shift div by 75
        id[k] = __ldg(&x[token]);
    }

    // Phase 2: oov_map gathers.
    #pragma unroll
    for (int k = 0; k < UNROLL; k++)
        row[k] = __ldg(&oov_map[id[k]]);

    // Phase 3+4: payload gather (default caching -> keeps w2v in L2) and
    // streaming store (evict-first -> does NOT displace w2v from L2).
    #pragma unroll
    for (int k = 0; k < UNROLL; k++) {
        int i     = base + k * STRIDE;
        int token = i / VEC;
        int chunk = i - token * VEC;
        const float4* src = (row[k] >= 0)
            ? (oov_embed + (long long)row[k] * VEC + chunk)
            : (w2v       + (long long)id[k]  * VEC + chunk);
        float4 v = __ldg(src);
        __stcs(&out[i], v);
    }
}

extern "C" void kernel_launch(void* const* d_in, const int* in_sizes, int n_in,
                              void* d_out, int out_size)
{
    const int*    x         = (const int*)   d_in[0];
    const float4* w2v       = (const float4*)d_in[1];
    const float4* oov_embed = (const float4*)d_in[2];
    const int*    oov_map   = (const int*)   d_in[3];
    float4*       out       = (float4*)d_out;

    iov_gather_cs_kernel<<<BLOCKS, THREADS>>>(x, w2v, oov_embed, oov_map, out);
}